// round 7
// baseline (speedup 1.0000x reference)
#include <cuda_runtime.h>
#include <math.h>
#include <stdint.h>

#define BB 16
#define NN 4096
#define NP 1024
#define NS 32
#define M_TOTAL (BB*NP*NS)   /* 524288 */
#define PP  132              /* pgemm A pitch (scalar path) */
#define PA1 640              /* gemm1 A floats per k2 row: 32 chunks x 20 */
#define PW1 160              /* gemm1 W floats per k2 row:  8 chunks x 20 */
#define PA2 320              /* gemm2 A floats per k2 row: 16 chunks x 20 */
#define PW2 320              /* gemm2 W floats per k2 row: 16 chunks x 20 */

typedef unsigned long long ull;

// ---------------------------------------------------------------------------
// Packed f32x2 helpers (bit-identical to 2x scalar fma.rn)
// ---------------------------------------------------------------------------
__device__ __forceinline__ void ffma2(ull& acc, ull a, ull w) {
    asm("fma.rn.f32x2 %0, %1, %2, %0;" : "+l"(acc) : "l"(a), "l"(w));
}
__device__ __forceinline__ float2 unpack2(ull v) {
    float2 r;
    asm("mov.b64 {%0, %1}, %2;" : "=f"(r.x), "=f"(r.y) : "l"(v));
    return r;
}
// k-pair chunked layout: offset in floats for (k2, idx, e)
//   = k2*P + (idx>>3)*20 + (idx&7)*2 + e        (16B pad per 8-idx chunk)
#define KP_OFF(idx) (((idx) >> 3)*20 + ((idx) & 7)*2)

// ---------------------------------------------------------------------------
// Scratch
// ---------------------------------------------------------------------------
__device__ float g_P[(size_t)BB*NN*64];       // pts-part of layer0   16.8 MB
__device__ float g_new_xyz[BB*NP*3];
__device__ int   g_idx[M_TOTAL];
__device__ float g_y1[(size_t)M_TOTAL*64];    // layer1 pre-BN       134 MB
__device__ float g_gmax[(size_t)BB*NP*128];
__device__ float g_gmin[(size_t)BB*NP*128];
__device__ float g_pS[4096*128];
__device__ float g_pQ[4096*128];
__device__ float g_mu[128];
__device__ float g_rs[128];

// ---------------------------------------------------------------------------
// 1) FPS: 512 thr, 8 pts/thread, one barrier per iteration (R5 config).
// ---------------------------------------------------------------------------
__global__ void fps_kernel(const float* __restrict__ xyz, float* __restrict__ out) {
    int b = blockIdx.x, tid = threadIdx.x;     // 512 threads
    int lane = tid & 31, wp = tid >> 5;
    const float* xb = xyz + (size_t)b*3*NN;
    float px[8], py[8], pz[8], dd[8];
    #pragma unroll
    for (int i = 0; i < 8; i++) {
        int n = tid + i*512;
        px[i] = xb[n]; py[i] = xb[NN+n]; pz[i] = xb[2*NN+n];
        dd[i] = 1e10f;
    }
    __shared__ unsigned s_wv[2][16];
    __shared__ int      s_wi[2][16];
    __shared__ int      s_fps[NP];
    if (tid == 0) s_fps[0] = 0;
    int far = 0;
    for (int it = 1; it < NP; ++it) {
        float cx = __ldg(xb + far);
        float cy = __ldg(xb + NN + far);
        float cz = __ldg(xb + 2*NN + far);
        unsigned bv = 0u, bi = 0x7fffffffu;
        #pragma unroll
        for (int i = 0; i < 8; i++) {
            float dx = __fsub_rn(px[i], cx);
            float dy = __fsub_rn(py[i], cy);
            float dz = __fsub_rn(pz[i], cz);
            float d  = __fadd_rn(__fadd_rn(__fmul_rn(dx,dx), __fmul_rn(dy,dy)),
                                 __fmul_rn(dz,dz));
            dd[i] = fminf(dd[i], d);
            unsigned vb = __float_as_uint(dd[i]);
            if (vb > bv) { bv = vb; bi = (unsigned)(tid + i*512); }
        }
        unsigned wmax = __reduce_max_sync(0xffffffffu, bv);
        unsigned cand = (bv == wmax) ? bi : 0x7fffffffu;
        unsigned wi   = __reduce_min_sync(0xffffffffu, cand);
        int buf = it & 1;
        if (lane == 0) { s_wv[buf][wp] = wmax; s_wi[buf][wp] = (int)wi; }
        __syncthreads();
        unsigned v  = (lane < 16) ? s_wv[buf][lane] : 0u;
        unsigned ix = (lane < 16) ? (unsigned)s_wi[buf][lane] : 0x7fffffffu;
        unsigned m2 = __reduce_max_sync(0xffffffffu, v);
        unsigned c2 = (v == m2) ? ix : 0x7fffffffu;
        far = (int)__reduce_min_sync(0xffffffffu, c2);
        if (tid == 0) s_fps[it] = far;
    }
    __syncthreads();
    for (int s = tid; s < NP; s += 512) {
        int j = s_fps[s];
        float x = xb[j], y = xb[NN+j], z = xb[2*NN+j];
        out[(size_t)b*3*NP + s]        = x;
        out[(size_t)b*3*NP + NP + s]   = y;
        out[(size_t)b*3*NP + 2*NP + s] = z;
        float* nx = g_new_xyz + ((size_t)b*NP + s)*3;
        nx[0] = x; nx[1] = y; nx[2] = z;
    }
}

// ---------------------------------------------------------------------------
// 2) Ball query (unchanged)
// ---------------------------------------------------------------------------
__global__ void ball_query_kernel(const float* __restrict__ xyz) {
    int gt   = blockIdx.x * blockDim.x + threadIdx.x;
    int warp = gt >> 5;
    int lane = gt & 31;
    if (warp >= BB*NP) return;
    int b = warp >> 10;
    const float* xb = xyz + (size_t)b*3*NN;
    const float* nx = g_new_xyz + (size_t)warp*3;
    float cx = nx[0], cy = nx[1], cz = nx[2];
    float ssrc = __fadd_rn(__fadd_rn(__fmul_rn(cx,cx), __fmul_rn(cy,cy)), __fmul_rn(cz,cz));
    const float R2 = 0.04f;
    int cnt = 0, first = -1;
    int* op = g_idx + (size_t)warp*NS;
    for (int j0 = 0; j0 < NN && cnt < NS; j0 += 32) {
        int j = j0 + lane;
        float x = xb[j], y = xb[NN+j], z = xb[2*NN+j];
        float sdst = __fadd_rn(__fadd_rn(__fmul_rn(x,x), __fmul_rn(y,y)), __fmul_rn(z,z));
        float dot  = __fadd_rn(__fadd_rn(__fmul_rn(cx,x), __fmul_rn(cy,y)), __fmul_rn(cz,z));
        float d = __fadd_rn(__fadd_rn(__fmul_rn(-2.0f, dot), ssrc), sdst);
        bool in = !(d > R2);
        unsigned m = __ballot_sync(0xffffffffu, in);
        if (first < 0 && m) first = j0 + __ffs(m) - 1;
        if (in) {
            int slot = cnt + __popc(m & ((1u << lane) - 1u));
            if (slot < NS) op[slot] = j;
        }
        cnt += __popc(m);
    }
    if (cnt < NS) {
        if (first < 0) first = NN - 1;
        for (int slot = cnt + lane; slot < NS; slot += 32) op[slot] = first;
    }
}

// ---------------------------------------------------------------------------
#define FMA8(a, w0, w1, accrow) \
    accrow[0] += a*w0.x; accrow[1] += a*w0.y; accrow[2] += a*w0.z; accrow[3] += a*w0.w; \
    accrow[4] += a*w1.x; accrow[5] += a*w1.y; accrow[6] += a*w1.z; accrow[7] += a*w1.w;

// W fill: [64][ldw] global slice -> Wlo/Whi [64][32] (pgemm scalar path)
__device__ __forceinline__ void fill_w64(float* Wlo, float* Whi,
                                         const float* __restrict__ w, int ldw,
                                         int c0, int tid) {
    for (int i = tid; i < 64*64; i += 256) {
        int k = i >> 6, c = i & 63;
        float v = w[k*ldw + c0 + c];
        int cgg = c >> 3, t = c & 7;
        if (t < 4) Wlo[k*32 + cgg*4 + t]     = v;
        else       Whi[k*32 + cgg*4 + t - 4] = v;
    }
}

// ---------------------------------------------------------------------------
// 3) P = pts^T @ W0[3:67] + b0  (scalar path; small)
// ---------------------------------------------------------------------------
__global__ void __launch_bounds__(256, 4)
pgemm_kernel(const float* __restrict__ pts, const float* __restrict__ w0,
             const float* __restrict__ b0) {
    extern __shared__ __align__(16) float sm[];
    float* As  = sm;                 // [64][PP]
    float* Wlo = sm + 64*PP;
    float* Whi = Wlo + 64*32;
    int tid = threadIdx.x;
    int bx  = blockIdx.x;
    int b   = bx >> 5;
    int n0  = (bx & 31) * 128;
    fill_w64(Wlo, Whi, w0 + 3*64, 64, 0, tid);
    const float* pb = pts + (size_t)b*64*NN;
    for (int i = tid; i < 64*128; i += 256) {
        int c = i >> 7, r = i & 127;
        As[c*PP + r] = pb[(size_t)c*NN + n0 + r];
    }
    __syncthreads();
    int rg = tid >> 3, cg = tid & 7;
    float acc[4][8];
    #pragma unroll
    for (int i = 0; i < 4; i++)
        #pragma unroll
        for (int j = 0; j < 8; j++) acc[i][j] = 0.0f;
    {
        const float* ap = As + rg*4;
        const float* wl = Wlo + cg*4;
        const float* wh = Whi + cg*4;
        #pragma unroll 8
        for (int k = 0; k < 64; ++k) {
            float4 a  = *(const float4*)(ap + k*PP);
            float4 w0v = *(const float4*)(wl + k*32);
            float4 w1v = *(const float4*)(wh + k*32);
            FMA8(a.x, w0v, w1v, acc[0]);
            FMA8(a.y, w0v, w1v, acc[1]);
            FMA8(a.z, w0v, w1v, acc[2]);
            FMA8(a.w, w0v, w1v, acc[3]);
        }
    }
    float bb[8];
    #pragma unroll
    for (int j = 0; j < 8; j++) bb[j] = b0[cg*8 + j];
    #pragma unroll
    for (int i = 0; i < 4; i++) {
        size_t row = (size_t)b*NN + n0 + rg*4 + i;
        float4 v0 = make_float4(acc[i][0]+bb[0], acc[i][1]+bb[1], acc[i][2]+bb[2], acc[i][3]+bb[3]);
        float4 v1 = make_float4(acc[i][4]+bb[4], acc[i][5]+bb[5], acc[i][6]+bb[6], acc[i][7]+bb[7]);
        *(float4*)&g_P[row*64 + cg*8]     = v0;
        *(float4*)&g_P[row*64 + cg*8 + 4] = v1;
    }
}

// ---------------------------------------------------------------------------
// 4) stats of y0 (never materialized): y0 = P[j] + dxyz . W0[0:3]
// ---------------------------------------------------------------------------
__global__ void __launch_bounds__(256)
stats0_kernel(const float* __restrict__ xyz, const float* __restrict__ w0) {
    __shared__ float sdx[256], sdy[256], sdz[256];
    __shared__ int   sj[256];
    __shared__ __align__(16) float s_w0[192];
    __shared__ float redS[64*17], redQ[64*17];
    int tid = threadIdx.x;
    int m0  = blockIdx.x * 256;
    int b   = m0 >> 15;
    if (tid < 192) s_w0[tid] = w0[tid];
    {
        int r = tid;
        int j = g_idx[m0 + r];
        sj[r] = j;
        const float* xb = xyz + (size_t)b*3*NN;
        const float* nx = g_new_xyz + (size_t)((m0 + r) >> 5)*3;
        sdx[r] = __fsub_rn(xb[j],      nx[0]);
        sdy[r] = __fsub_rn(xb[NN+j],   nx[1]);
        sdz[r] = __fsub_rn(xb[2*NN+j], nx[2]);
    }
    __syncthreads();
    int q  = tid >> 4;
    int rl = tid & 15;
    float4 wx = *(const float4*)(s_w0 + q*4);
    float4 wy = *(const float4*)(s_w0 + 64 + q*4);
    float4 wz = *(const float4*)(s_w0 + 128 + q*4);
    float sx=0,sy=0,sz=0,sw=0, qx=0,qy=0,qz=0,qw=0;
    const float* Pb = g_P + (size_t)b*NN*64;
    for (int n = 0; n < 16; n++) {
        int r = rl + n*16;
        float4 p = *(const float4*)(Pb + (size_t)sj[r]*64 + q*4);
        float dx = sdx[r], dy = sdy[r], dz = sdz[r];
        float yx = p.x + dx*wx.x + dy*wy.x + dz*wz.x;
        float yy = p.y + dx*wx.y + dy*wy.y + dz*wz.y;
        float yz = p.z + dx*wx.z + dy*wy.z + dz*wz.z;
        float yw = p.w + dx*wx.w + dy*wy.w + dz*wz.w;
        sx += yx; sy += yy; sz += yz; sw += yw;
        qx += yx*yx; qy += yy*yy; qz += yz*yz; qw += yw*yw;
    }
    redS[(4*q+0)*17 + rl] = sx; redQ[(4*q+0)*17 + rl] = qx;
    redS[(4*q+1)*17 + rl] = sy; redQ[(4*q+1)*17 + rl] = qy;
    redS[(4*q+2)*17 + rl] = sz; redQ[(4*q+2)*17 + rl] = qz;
    redS[(4*q+3)*17 + rl] = sw; redQ[(4*q+3)*17 + rl] = qw;
    __syncthreads();
    if (tid < 64) {
        float ss = 0.0f, sq = 0.0f;
        #pragma unroll
        for (int u = 0; u < 16; u++) { ss += redS[tid*17+u]; sq += redQ[tid*17+u]; }
        g_pS[blockIdx.x*64 + tid] = ss;
        g_pQ[blockIdx.x*64 + tid] = sq;
    }
}

// ---------------------------------------------------------------------------
// 5) layer1: 256x64 tile, k-pair FFMA2 8x8 acc. A = BN0+ReLU(y0 on the fly).
// ---------------------------------------------------------------------------
__global__ void __launch_bounds__(256, 1)
gemm1_kernel(const float* __restrict__ xyz, const float* __restrict__ w0,
             const float* __restrict__ w1, const float* __restrict__ b1,
             const float* __restrict__ gam0, const float* __restrict__ bet0) {
    extern __shared__ __align__(16) float sm[];
    float* As2 = sm;                 // [32 k2][PA1]
    float* Wp  = sm + 32*PA1;        // [32 k2][PW1]
    __shared__ float sdx[256], sdy[256], sdz[256];
    __shared__ int   sj[256];
    __shared__ __align__(16) float s_w0[192];
    int tid = threadIdx.x;
    int m0  = blockIdx.x * 256;
    int b   = m0 >> 15;
    // W fill (k-pair chunked)
    for (int i = tid; i < 64*64; i += 256) {
        int k = i >> 6, c = i & 63;
        Wp[(k >> 1)*PW1 + KP_OFF(c) + (k & 1)] = w1[i];
    }
    if (tid < 192) s_w0[tid] = w0[tid];
    {
        int r = tid;
        int j = g_idx[m0 + r];
        sj[r] = j;
        const float* xb = xyz + (size_t)b*3*NN;
        const float* nx = g_new_xyz + (size_t)((m0 + r) >> 5)*3;
        sdx[r] = __fsub_rn(xb[j],      nx[0]);
        sdy[r] = __fsub_rn(xb[NN+j],   nx[1]);
        sdz[r] = __fsub_rn(xb[2*NN+j], nx[2]);
    }
    __syncthreads();
    {
        int q  = tid >> 4;    // channel quad 0..15
        int rl = tid & 15;
        float4 wx = *(const float4*)(s_w0 + q*4);
        float4 wy = *(const float4*)(s_w0 + 64 + q*4);
        float4 wz = *(const float4*)(s_w0 + 128 + q*4);
        float sc[4], sh[4];
        #pragma unroll
        for (int t = 0; t < 4; t++) {
            int k = q*4 + t;
            sc[t] = g_rs[k]*gam0[k];
            sh[t] = bet0[k] - g_mu[k]*sc[t];
        }
        const float* Pb = g_P + (size_t)b*NN*64;
        float* rowA = As2 + (q*2)*PA1;
        float* rowB = As2 + (q*2+1)*PA1;
        for (int n = 0; n < 16; n++) {
            int r = rl + n*16;
            float4 p = *(const float4*)(Pb + (size_t)sj[r]*64 + q*4);
            float dx = sdx[r], dy = sdy[r], dz = sdz[r];
            float v0 = fmaxf((p.x + dx*wx.x + dy*wy.x + dz*wz.x)*sc[0] + sh[0], 0.0f);
            float v1 = fmaxf((p.y + dx*wx.y + dy*wy.y + dz*wz.y)*sc[1] + sh[1], 0.0f);
            float v2 = fmaxf((p.z + dx*wx.z + dy*wy.z + dz*wz.z)*sc[2] + sh[2], 0.0f);
            float v3 = fmaxf((p.w + dx*wx.w + dy*wy.w + dz*wz.w)*sc[3] + sh[3], 0.0f);
            int off = KP_OFF(r);
            *(float2*)(rowA + off) = make_float2(v0, v1);
            *(float2*)(rowB + off) = make_float2(v2, v3);
        }
    }
    __syncthreads();
    int rg = tid >> 3, cg = tid & 7;       // rg 0..31 (8 rows), cg 0..7 (8 cols)
    ull acc2[8][8];
    #pragma unroll
    for (int i = 0; i < 8; i++)
        #pragma unroll
        for (int j = 0; j < 8; j++) acc2[i][j] = 0ull;
    {
        const char* ap = (const char*)As2 + rg*80;
        const char* wq = (const char*)Wp  + cg*80;
        #pragma unroll 2
        for (int k2 = 0; k2 < 32; ++k2) {
            ulonglong2 A0 = *(const ulonglong2*)(ap + k2*(PA1*4));
            ulonglong2 A1 = *(const ulonglong2*)(ap + k2*(PA1*4) + 16);
            ulonglong2 A2 = *(const ulonglong2*)(ap + k2*(PA1*4) + 32);
            ulonglong2 A3 = *(const ulonglong2*)(ap + k2*(PA1*4) + 48);
            ulonglong2 W0 = *(const ulonglong2*)(wq + k2*(PW1*4));
            ulonglong2 W1 = *(const ulonglong2*)(wq + k2*(PW1*4) + 16);
            ulonglong2 W2 = *(const ulonglong2*)(wq + k2*(PW1*4) + 32);
            ulonglong2 W3 = *(const ulonglong2*)(wq + k2*(PW1*4) + 48);
            ull a[8] = {A0.x, A0.y, A1.x, A1.y, A2.x, A2.y, A3.x, A3.y};
            ull w[8] = {W0.x, W0.y, W1.x, W1.y, W2.x, W2.y, W3.x, W3.y};
            #pragma unroll
            for (int i = 0; i < 8; i++)
                #pragma unroll
                for (int j = 0; j < 8; j++)
                    ffma2(acc2[i][j], a[i], w[j]);
        }
    }
    float acc[8][8];
    #pragma unroll
    for (int i = 0; i < 8; i++)
        #pragma unroll
        for (int j = 0; j < 8; j++) {
            float2 u = unpack2(acc2[i][j]);
            acc[i][j] = u.x + u.y;
        }
    float bb[8];
    #pragma unroll
    for (int j = 0; j < 8; j++) bb[j] = b1[cg*8 + j];
    #pragma unroll
    for (int i = 0; i < 8; i++)
        #pragma unroll
        for (int j = 0; j < 8; j++) acc[i][j] += bb[j];
    #pragma unroll
    for (int i = 0; i < 8; i++) {
        size_t row = (size_t)(m0 + rg*8 + i);
        float4 v0 = make_float4(acc[i][0], acc[i][1], acc[i][2], acc[i][3]);
        float4 v1 = make_float4(acc[i][4], acc[i][5], acc[i][6], acc[i][7]);
        *(float4*)&g_y1[row*64 + cg*8]     = v0;
        *(float4*)&g_y1[row*64 + cg*8 + 4] = v1;
    }
    float s8[8], q8[8];
    #pragma unroll
    for (int j = 0; j < 8; j++) { s8[j] = 0.0f; q8[j] = 0.0f; }
    #pragma unroll
    for (int i = 0; i < 8; i++)
        #pragma unroll
        for (int j = 0; j < 8; j++) { s8[j] += acc[i][j]; q8[j] += acc[i][j]*acc[i][j]; }
    __syncthreads();
    float* rS = As2;            // [64][33]
    float* rQ = As2 + 64*33;
    #pragma unroll
    for (int j = 0; j < 8; j++) {
        rS[(cg*8 + j)*33 + rg] = s8[j];
        rQ[(cg*8 + j)*33 + rg] = q8[j];
    }
    __syncthreads();
    if (tid < 64) {
        float s = 0.0f, q = 0.0f;
        #pragma unroll 8
        for (int r = 0; r < 32; r++) { s += rS[tid*33 + r]; q += rQ[tid*33 + r]; }
        g_pS[blockIdx.x*64 + tid] = s;
        g_pQ[blockIdx.x*64 + tid] = q;
    }
}

// ---------------------------------------------------------------------------
// 6) layer2: 128x128 tile, k-pair FFMA2 8x8 acc. A = BN1+ReLU(y1) read once.
// ---------------------------------------------------------------------------
__global__ void __launch_bounds__(256, 1)
gemm2_kernel(const float* __restrict__ w2, const float* __restrict__ b2,
             const float* __restrict__ gam1, const float* __restrict__ bet1) {
    extern __shared__ __align__(16) float sm[];
    float* As2 = sm;                 // [32 k2][PA2]
    float* Wp  = sm + 32*PA2;        // [32 k2][PW2]
    int tid = threadIdx.x;
    int m0  = blockIdx.x * 128;
    for (int i = tid; i < 64*128; i += 256) {
        int k = i >> 7, c = i & 127;
        Wp[(k >> 1)*PW2 + KP_OFF(c) + (k & 1)] = w2[i];
    }
    {
        int q  = tid >> 4;
        int rl = tid & 15;
        float sc[4], sh[4];
        #pragma unroll
        for (int t = 0; t < 4; t++) {
            int k = q*4 + t;
            sc[t] = g_rs[k]*gam1[k];
            sh[t] = bet1[k] - g_mu[k]*sc[t];
        }
        float* rowA = As2 + (q*2)*PA2;
        float* rowB = As2 + (q*2+1)*PA2;
        for (int n = 0; n < 8; n++) {
            int r = rl + n*16;
            float4 p = *(const float4*)(g_y1 + (size_t)(m0 + r)*64 + q*4);
            float v0 = fmaxf(p.x*sc[0] + sh[0], 0.0f);
            float v1 = fmaxf(p.y*sc[1] + sh[1], 0.0f);
            float v2 = fmaxf(p.z*sc[2] + sh[2], 0.0f);
            float v3 = fmaxf(p.w*sc[3] + sh[3], 0.0f);
            int off = KP_OFF(r);
            *(float2*)(rowA + off) = make_float2(v0, v1);
            *(float2*)(rowB + off) = make_float2(v2, v3);
        }
    }
    __syncthreads();
    int rg = tid >> 4, cg = tid & 15;      // rg 0..15 (8 rows), cg 0..15 (8 cols)
    ull acc2[8][8];
    #pragma unroll
    for (int i = 0; i < 8; i++)
        #pragma unroll
        for (int j = 0; j < 8; j++) acc2[i][j] = 0ull;
    {
        const char* ap = (const char*)As2 + rg*80;
        const char* wq = (const char*)Wp  + cg*80;
        #pragma unroll 2
        for (int k2 = 0; k2 < 32; ++k2) {
            ulonglong2 A0 = *(const ulonglong2*)(ap + k2*(PA2*4));
            ulonglong2 A1 = *(const ulonglong2*)(ap + k2*(PA2*4) + 16);
            ulonglong2 A2 = *(const ulonglong2*)(ap + k2*(PA2*4) + 32);
            ulonglong2 A3 = *(const ulonglong2*)(ap + k2*(PA2*4) + 48);
            ulonglong2 W0 = *(const ulonglong2*)(wq + k2*(PW2*4));
            ulonglong2 W1 = *(const ulonglong2*)(wq + k2*(PW2*4) + 16);
            ulonglong2 W2 = *(const ulonglong2*)(wq + k2*(PW2*4) + 32);
            ulonglong2 W3 = *(const ulonglong2*)(wq + k2*(PW2*4) + 48);
            ull a[8] = {A0.x, A0.y, A1.x, A1.y, A2.x, A2.y, A3.x, A3.y};
            ull w[8] = {W0.x, W0.y, W1.x, W1.y, W2.x, W2.y, W3.x, W3.y};
            #pragma unroll
            for (int i = 0; i < 8; i++)
                #pragma unroll
                for (int j = 0; j < 8; j++)
                    ffma2(acc2[i][j], a[i], w[j]);
        }
    }
    float acc[8][8];
    #pragma unroll
    for (int i = 0; i < 8; i++)
        #pragma unroll
        for (int j = 0; j < 8; j++) {
            float2 u = unpack2(acc2[i][j]);
            acc[i][j] = u.x + u.y;
        }
    float bb[8];
    #pragma unroll
    for (int j = 0; j < 8; j++) bb[j] = b2[cg*8 + j];
    #pragma unroll
    for (int i = 0; i < 8; i++)
        #pragma unroll
        for (int j = 0; j < 8; j++) acc[i][j] += bb[j];
    float s8[8], q8[8], mx8[8], mn8[8];
    #pragma unroll
    for (int j = 0; j < 8; j++) {
        s8[j] = acc[0][j]; q8[j] = acc[0][j]*acc[0][j];
        mx8[j] = acc[0][j]; mn8[j] = acc[0][j];
    }
    #pragma unroll
    for (int i = 1; i < 8; i++)
        #pragma unroll
        for (int j = 0; j < 8; j++) {
            s8[j] += acc[i][j]; q8[j] += acc[i][j]*acc[i][j];
            mx8[j] = fmaxf(mx8[j], acc[i][j]);
            mn8[j] = fminf(mn8[j], acc[i][j]);
        }
    __syncthreads();
    float* rS   = As2;               // [128][17]
    float* rQ   = As2 + 128*17;
    float* rmax = Wp;                // [16][132]
    float* rmin = Wp + 16*132;
    #pragma unroll
    for (int j = 0; j < 8; j++) {
        rS[(cg*8 + j)*17 + rg] = s8[j];
        rQ[(cg*8 + j)*17 + rg] = q8[j];
        rmax[rg*132 + cg*8 + j] = mx8[j];
        rmin[rg*132 + cg*8 + j] = mn8[j];
    }
    __syncthreads();
    if (tid < 128) {
        float s = 0.0f, q = 0.0f;
        #pragma unroll
        for (int r = 0; r < 16; r++) { s += rS[tid*17 + r]; q += rQ[tid*17 + r]; }
        g_pS[blockIdx.x*128 + tid] = s;
        g_pQ[blockIdx.x*128 + tid] = q;
    }
    for (int i = tid; i < 512; i += 256) {
        int g = i >> 7, c = i & 127;
        float mx = rmax[(g*4 + 0)*132 + c];
        float mn = rmin[(g*4 + 0)*132 + c];
        #pragma unroll
        for (int u = 1; u < 4; u++) {
            mx = fmaxf(mx, rmax[(g*4 + u)*132 + c]);
            mn = fminf(mn, rmin[(g*4 + u)*132 + c]);
        }
        size_t grp = (size_t)blockIdx.x*4 + g;
        g_gmax[grp*128 + c] = mx;
        g_gmin[grp*128 + c] = mn;
    }
}

// ---------------------------------------------------------------------------
// 7) finalize stats
// ---------------------------------------------------------------------------
__global__ void finalize_stats_kernel(int C, int nblk) {
    __shared__ double shs[512], shq[512];
    int tid = threadIdx.x;
    int c   = tid & (C - 1);
    int rep = tid / C;
    int nrep = 512 / C;
    int per  = nblk / nrep;
    double s = 0.0, q = 0.0;
    for (int b = rep*per; b < (rep+1)*per; b++) {
        s += (double)g_pS[b*C + c];
        q += (double)g_pQ[b*C + c];
    }
    shs[tid] = s; shq[tid] = q;
    __syncthreads();
    if (rep == 0) {
        for (int r = 1; r < nrep; r++) { s += shs[r*C + c]; q += shq[r*C + c]; }
        double n = (double)M_TOTAL;
        double m = s / n;
        double var = q / n - m*m;
        g_mu[c] = (float)m;
        g_rs[c] = (float)(1.0 / sqrt(var + 1e-5));
    }
}

// ---------------------------------------------------------------------------
// 8) final: BN2+ReLU on group extrema, transpose -> out [B,128,NP]
// ---------------------------------------------------------------------------
__global__ void final_out_kernel(const float* __restrict__ gam2,
                                 const float* __restrict__ bet2,
                                 float* __restrict__ out) {
    extern __shared__ float sh[];             // [128 c][129]
    int b  = blockIdx.x;
    int s0 = blockIdx.y * 128;
    int tid = threadIdx.x;                    // 256
    for (int i = tid; i < 128*128; i += 256) {
        int s = i >> 7, c = i & 127;
        float slope = g_rs[c]*gam2[c];
        size_t gidx = ((size_t)(b*NP + s0 + s))*128 + c;
        float raw = (slope >= 0.0f) ? g_gmax[gidx] : g_gmin[gidx];
        float v = (raw - g_mu[c])*slope + bet2[c];
        sh[c*129 + s] = fmaxf(v, 0.0f);
    }
    __syncthreads();
    float* ob = out + (size_t)BB*3*NP + (size_t)b*128*NP + s0;
    for (int i = tid; i < 128*128; i += 256) {
        int c = i >> 7, s = i & 127;
        ob[(size_t)c*NP + s] = sh[c*129 + s];
    }
}

// ---------------------------------------------------------------------------
extern "C" void kernel_launch(void* const* d_in, const int* in_sizes, int n_in,
                              void* d_out, int out_size) {
    const float* xyz = (const float*)d_in[0];
    const float* pts = (const float*)d_in[1];
    const float* w0  = (const float*)d_in[2];
    const float* b0  = (const float*)d_in[3];
    const float* g0  = (const float*)d_in[4];
    const float* be0 = (const float*)d_in[5];
    const float* w1  = (const float*)d_in[6];
    const float* b1  = (const float*)d_in[7];
    const float* g1  = (const float*)d_in[8];
    const float* be1 = (const float*)d_in[9];
    const float* w2  = (const float*)d_in[10];
    const float* b2  = (const float*)d_in[11];
    const float* g2  = (const float*)d_in[12];
    const float* be2 = (const float*)d_in[13];
    float* out = (float*)d_out;

    const int smemP = (64*PP + 64*64) * 4;        // 50176 B
    const int smem1 = (32*PA1 + 32*PW1) * 4;      // 102400 B
    const int smem2 = (32*PA2 + 32*PW2) * 4;      // 81920 B
    const int smemF = 128*129*4;                  // 66048 B
    cudaFuncSetAttribute(pgemm_kernel, cudaFuncAttributeMaxDynamicSharedMemorySize, smemP);
    cudaFuncSetAttribute(gemm1_kernel, cudaFuncAttributeMaxDynamicSharedMemorySize, smem1);
    cudaFuncSetAttribute(gemm2_kernel, cudaFuncAttributeMaxDynamicSharedMemorySize, smem2);
    cudaFuncSetAttribute(final_out_kernel, cudaFuncAttributeMaxDynamicSharedMemorySize, smemF);

    fps_kernel<<<16, 512>>>(xyz, out);
    ball_query_kernel<<<2048, 256>>>(xyz);
    pgemm_kernel<<<512, 256, smemP>>>(pts, w0, b0);

    stats0_kernel<<<2048, 256>>>(xyz, w0);
    finalize_stats_kernel<<<1, 512>>>(64, 2048);

    gemm1_kernel<<<2048, 256, smem1>>>(xyz, w0, w1, b1, g0, be0);
    finalize_stats_kernel<<<1, 512>>>(64, 2048);

    gemm2_kernel<<<4096, 256, smem2>>>(w2, b2, g1, be1);
    finalize_stats_kernel<<<1, 512>>>(128, 4096);

    final_out_kernel<<<dim3(16, 8), 256, smemF>>>(g2, be2, out);
}

// round 12
// speedup vs baseline: 1.0787x; 1.0787x over previous
#include <cuda_runtime.h>
#include <cuda_bf16.h>
#include <mma.h>
#include <math.h>
#include <stdint.h>

using namespace nvcuda;

#define BB 16
#define NN 4096
#define NP 1024
#define NS 32
#define M_TOTAL (BB*NP*NS)   /* 524288 */
#define PP  132              /* pgemm A pitch */
#define P1  260              /* gemm1 A pitch (256 rows + pad) */
#define AP  72               /* gemm2 A smem pitch (bf16 elems) */
#define BP  136              /* gemm2 B smem pitch (bf16 elems) */
#define DP  136              /* gemm2 D smem pitch (f32 elems) */

typedef unsigned long long ull;

// ---------------------------------------------------------------------------
// f32x2 helpers (gemm1, bit-identical to scalar fma.rn)
// ---------------------------------------------------------------------------
__device__ __forceinline__ void ffma2(ull& acc, ull a, ull w) {
    asm("fma.rn.f32x2 %0, %1, %2, %0;" : "+l"(acc) : "l"(a), "l"(w));
}
__device__ __forceinline__ ull pack2(float x) {
    ull r;
    asm("mov.b64 %0, {%1, %1};" : "=l"(r) : "f"(x));
    return r;
}
__device__ __forceinline__ float2 unpack2(ull v) {
    float2 r;
    asm("mov.b64 {%0, %1}, %2;" : "=f"(r.x), "=f"(r.y) : "l"(v));
    return r;
}

// ---------------------------------------------------------------------------
// Scratch
// ---------------------------------------------------------------------------
__device__ float g_P[(size_t)BB*NN*64];
__device__ float g_new_xyz[BB*NP*3];
__device__ int   g_idx[M_TOTAL];
__device__ float g_y1[(size_t)M_TOTAL*64];
__device__ float g_gmax[(size_t)BB*NP*128];
__device__ float g_gmin[(size_t)BB*NP*128];
__device__ float g_pS[4096*128];
__device__ float g_pQ[4096*128];
__device__ float g_mu[128];
__device__ float g_rs[128];

// ---------------------------------------------------------------------------
// 1) FPS (1024 thr, 4 pts/thread, one barrier/iter)
// ---------------------------------------------------------------------------
__global__ void __launch_bounds__(1024, 1)
fps_kernel(const float* __restrict__ xyz, float* __restrict__ out) {
    int b = blockIdx.x, tid = threadIdx.x;
    int lane = tid & 31, wp = tid >> 5;
    const float* xb = xyz + (size_t)b*3*NN;
    float px[4], py[4], pz[4], dd[4];
    #pragma unroll
    for (int i = 0; i < 4; i++) {
        int n = tid + i*1024;
        px[i] = xb[n]; py[i] = xb[NN+n]; pz[i] = xb[2*NN+n];
        dd[i] = 1e10f;
    }
    __shared__ unsigned s_wv[2][32];
    __shared__ int      s_wi[2][32];
    __shared__ int      s_fps[NP];
    if (tid == 0) s_fps[0] = 0;
    int far = 0;
    for (int it = 1; it < NP; ++it) {
        float cx = __ldg(xb + far);
        float cy = __ldg(xb + NN + far);
        float cz = __ldg(xb + 2*NN + far);
        unsigned bv = 0u, bi = 0x7fffffffu;
        #pragma unroll
        for (int i = 0; i < 4; i++) {
            float dx = __fsub_rn(px[i], cx);
            float dy = __fsub_rn(py[i], cy);
            float dz = __fsub_rn(pz[i], cz);
            float d  = __fadd_rn(__fadd_rn(__fmul_rn(dx,dx), __fmul_rn(dy,dy)),
                                 __fmul_rn(dz,dz));
            dd[i] = fminf(dd[i], d);
            unsigned vb = __float_as_uint(dd[i]);
            if (vb > bv) { bv = vb; bi = (unsigned)(tid + i*1024); }
        }
        unsigned wmax = __reduce_max_sync(0xffffffffu, bv);
        unsigned cand = (bv == wmax) ? bi : 0x7fffffffu;
        unsigned wi   = __reduce_min_sync(0xffffffffu, cand);
        int buf = it & 1;
        if (lane == 0) { s_wv[buf][wp] = wmax; s_wi[buf][wp] = (int)wi; }
        __syncthreads();
        unsigned v  = s_wv[buf][lane];
        unsigned ix = (unsigned)s_wi[buf][lane];
        unsigned m2 = __reduce_max_sync(0xffffffffu, v);
        unsigned c2 = (v == m2) ? ix : 0x7fffffffu;
        far = (int)__reduce_min_sync(0xffffffffu, c2);
        if (tid == 0) s_fps[it] = far;
    }
    __syncthreads();
    for (int s = tid; s < NP; s += 1024) {
        int j = s_fps[s];
        float x = xb[j], y = xb[NN+j], z = xb[2*NN+j];
        out[(size_t)b*3*NP + s]        = x;
        out[(size_t)b*3*NP + NP + s]   = y;
        out[(size_t)b*3*NP + 2*NP + s] = z;
        float* nx = g_new_xyz + ((size_t)b*NP + s)*3;
        nx[0] = x; nx[1] = y; nx[2] = z;
    }
}

// ---------------------------------------------------------------------------
// 2) Ball query (unchanged)
// ---------------------------------------------------------------------------
__global__ void ball_query_kernel(const float* __restrict__ xyz) {
    int gt   = blockIdx.x * blockDim.x + threadIdx.x;
    int warp = gt >> 5;
    int lane = gt & 31;
    if (warp >= BB*NP) return;
    int b = warp >> 10;
    const float* xb = xyz + (size_t)b*3*NN;
    const float* nx = g_new_xyz + (size_t)warp*3;
    float cx = nx[0], cy = nx[1], cz = nx[2];
    float ssrc = __fadd_rn(__fadd_rn(__fmul_rn(cx,cx), __fmul_rn(cy,cy)), __fmul_rn(cz,cz));
    const float R2 = 0.04f;
    int cnt = 0, first = -1;
    int* op = g_idx + (size_t)warp*NS;
    for (int j0 = 0; j0 < NN && cnt < NS; j0 += 32) {
        int j = j0 + lane;
        float x = xb[j], y = xb[NN+j], z = xb[2*NN+j];
        float sdst = __fadd_rn(__fadd_rn(__fmul_rn(x,x), __fmul_rn(y,y)), __fmul_rn(z,z));
        float dot  = __fadd_rn(__fadd_rn(__fmul_rn(cx,x), __fmul_rn(cy,y)), __fmul_rn(cz,z));
        float d = __fadd_rn(__fadd_rn(__fmul_rn(-2.0f, dot), ssrc), sdst);
        bool in = !(d > R2);
        unsigned m = __ballot_sync(0xffffffffu, in);
        if (first < 0 && m) first = j0 + __ffs(m) - 1;
        if (in) {
            int slot = cnt + __popc(m & ((1u << lane) - 1u));
            if (slot < NS) op[slot] = j;
        }
        cnt += __popc(m);
    }
    if (cnt < NS) {
        if (first < 0) first = NN - 1;
        for (int slot = cnt + lane; slot < NS; slot += 32) op[slot] = first;
    }
}

// ---------------------------------------------------------------------------
#define FMA8(a, w0, w1, accrow) \
    accrow[0] += a*w0.x; accrow[1] += a*w0.y; accrow[2] += a*w0.z; accrow[3] += a*w0.w; \
    accrow[4] += a*w1.x; accrow[5] += a*w1.y; accrow[6] += a*w1.z; accrow[7] += a*w1.w;

__device__ __forceinline__ void fill_w64(float* Wlo, float* Whi,
                                         const float* __restrict__ w, int ldw,
                                         int c0, int tid) {
    for (int i = tid; i < 64*64; i += 256) {
        int k = i >> 6, c = i & 63;
        float v = w[k*ldw + c0 + c];
        int cgg = c >> 3, t = c & 7;
        if (t < 4) Wlo[k*32 + cgg*4 + t]     = v;
        else       Whi[k*32 + cgg*4 + t - 4] = v;
    }
}

// ---------------------------------------------------------------------------
// 3) P = pts^T @ W0[3:67] + b0
// ---------------------------------------------------------------------------
__global__ void __launch_bounds__(256, 4)
pgemm_kernel(const float* __restrict__ pts, const float* __restrict__ w0,
             const float* __restrict__ b0) {
    extern __shared__ __align__(16) float sm[];
    float* As  = sm;
    float* Wlo = sm + 64*PP;
    float* Whi = Wlo + 64*32;
    int tid = threadIdx.x;
    int bx  = blockIdx.x;
    int b   = bx >> 5;
    int n0  = (bx & 31) * 128;
    fill_w64(Wlo, Whi, w0 + 3*64, 64, 0, tid);
    const float* pb = pts + (size_t)b*64*NN;
    for (int i = tid; i < 64*128; i += 256) {
        int c = i >> 7, r = i & 127;
        As[c*PP + r] = pb[(size_t)c*NN + n0 + r];
    }
    __syncthreads();
    int rg = tid >> 3, cg = tid & 7;
    float acc[4][8];
    #pragma unroll
    for (int i = 0; i < 4; i++)
        #pragma unroll
        for (int j = 0; j < 8; j++) acc[i][j] = 0.0f;
    {
        const float* ap = As + rg*4;
        const float* wl = Wlo + cg*4;
        const float* wh = Whi + cg*4;
        #pragma unroll 8
        for (int k = 0; k < 64; ++k) {
            float4 a  = *(const float4*)(ap + k*PP);
            float4 w0v = *(const float4*)(wl + k*32);
            float4 w1v = *(const float4*)(wh + k*32);
            FMA8(a.x, w0v, w1v, acc[0]);
            FMA8(a.y, w0v, w1v, acc[1]);
            FMA8(a.z, w0v, w1v, acc[2]);
            FMA8(a.w, w0v, w1v, acc[3]);
        }
    }
    float bb[8];
    #pragma unroll
    for (int j = 0; j < 8; j++) bb[j] = b0[cg*8 + j];
    #pragma unroll
    for (int i = 0; i < 4; i++) {
        size_t row = (size_t)b*NN + n0 + rg*4 + i;
        float4 v0 = make_float4(acc[i][0]+bb[0], acc[i][1]+bb[1], acc[i][2]+bb[2], acc[i][3]+bb[3]);
        float4 v1 = make_float4(acc[i][4]+bb[4], acc[i][5]+bb[5], acc[i][6]+bb[6], acc[i][7]+bb[7]);
        *(float4*)&g_P[row*64 + cg*8]     = v0;
        *(float4*)&g_P[row*64 + cg*8 + 4] = v1;
    }
}

// ---------------------------------------------------------------------------
// 4) stats of y0 (never materialized)
// ---------------------------------------------------------------------------
__global__ void __launch_bounds__(256)
stats0_kernel(const float* __restrict__ xyz, const float* __restrict__ w0) {
    __shared__ float sdx[256], sdy[256], sdz[256];
    __shared__ int   sj[256];
    __shared__ __align__(16) float s_w0[192];
    __shared__ float redS[64*17], redQ[64*17];
    int tid = threadIdx.x;
    int m0  = blockIdx.x * 256;
    int b   = m0 >> 15;
    if (tid < 192) s_w0[tid] = w0[tid];
    {
        int r = tid;
        int j = g_idx[m0 + r];
        sj[r] = j;
        const float* xb = xyz + (size_t)b*3*NN;
        const float* nx = g_new_xyz + (size_t)((m0 + r) >> 5)*3;
        sdx[r] = __fsub_rn(xb[j],      nx[0]);
        sdy[r] = __fsub_rn(xb[NN+j],   nx[1]);
        sdz[r] = __fsub_rn(xb[2*NN+j], nx[2]);
    }
    __syncthreads();
    int q  = tid >> 4;
    int rl = tid & 15;
    float4 wx = *(const float4*)(s_w0 + q*4);
    float4 wy = *(const float4*)(s_w0 + 64 + q*4);
    float4 wz = *(const float4*)(s_w0 + 128 + q*4);
    float sx=0,sy=0,sz=0,sw=0, qx=0,qy=0,qz=0,qw=0;
    const float* Pb = g_P + (size_t)b*NN*64;
    for (int n = 0; n < 16; n++) {
        int r = rl + n*16;
        float4 p = *(const float4*)(Pb + (size_t)sj[r]*64 + q*4);
        float dx = sdx[r], dy = sdy[r], dz = sdz[r];
        float yx = p.x + dx*wx.x + dy*wy.x + dz*wz.x;
        float yy = p.y + dx*wx.y + dy*wy.y + dz*wz.y;
        float yz = p.z + dx*wx.z + dy*wy.z + dz*wz.z;
        float yw = p.w + dx*wx.w + dy*wy.w + dz*wz.w;
        sx += yx; sy += yy; sz += yz; sw += yw;
        qx += yx*yx; qy += yy*yy; qz += yz*yz; qw += yw*yw;
    }
    redS[(4*q+0)*17 + rl] = sx; redQ[(4*q+0)*17 + rl] = qx;
    redS[(4*q+1)*17 + rl] = sy; redQ[(4*q+1)*17 + rl] = qy;
    redS[(4*q+2)*17 + rl] = sz; redQ[(4*q+2)*17 + rl] = qz;
    redS[(4*q+3)*17 + rl] = sw; redQ[(4*q+3)*17 + rl] = qw;
    __syncthreads();
    if (tid < 64) {
        float ss = 0.0f, sq = 0.0f;
        #pragma unroll
        for (int u = 0; u < 16; u++) { ss += redS[tid*17+u]; sq += redQ[tid*17+u]; }
        g_pS[blockIdx.x*64 + tid] = ss;
        g_pQ[blockIdx.x*64 + tid] = sq;
    }
}

// ---------------------------------------------------------------------------
// 5) layer1 (R6 f32x2 version, unchanged)
// ---------------------------------------------------------------------------
__global__ void __launch_bounds__(256, 2)
gemm1_kernel(const float* __restrict__ xyz, const float* __restrict__ w0,
             const float* __restrict__ w1, const float* __restrict__ b1,
             const float* __restrict__ gam0, const float* __restrict__ bet0) {
    extern __shared__ __align__(16) float sm[];
    float* As  = sm;                 // [64][P1]
    float* Wlo = sm + 64*P1;         // [64][32]
    float* Whi = Wlo + 64*32;
    __shared__ float sdx[256], sdy[256], sdz[256];
    __shared__ int   sj[256];
    __shared__ __align__(16) float s_w0[192];
    int tid = threadIdx.x;
    int m0  = blockIdx.x * 256;
    int b   = m0 >> 15;
    fill_w64(Wlo, Whi, w1, 64, 0, tid);
    if (tid < 192) s_w0[tid] = w0[tid];
    {
        int r = tid;
        int j = g_idx[m0 + r];
        sj[r] = j;
        const float* xb = xyz + (size_t)b*3*NN;
        const float* nx = g_new_xyz + (size_t)((m0 + r) >> 5)*3;
        sdx[r] = __fsub_rn(xb[j],      nx[0]);
        sdy[r] = __fsub_rn(xb[NN+j],   nx[1]);
        sdz[r] = __fsub_rn(xb[2*NN+j], nx[2]);
    }
    __syncthreads();
    {
        int q  = tid >> 4;
        int rl = tid & 15;
        float4 wx = *(const float4*)(s_w0 + q*4);
        float4 wy = *(const float4*)(s_w0 + 64 + q*4);
        float4 wz = *(const float4*)(s_w0 + 128 + q*4);
        float sc[4], sh[4];
        #pragma unroll
        for (int t = 0; t < 4; t++) {
            int k = q*4 + t;
            sc[t] = g_rs[k]*gam0[k];
            sh[t] = bet0[k] - g_mu[k]*sc[t];
        }
        const float* Pb = g_P + (size_t)b*NN*64;
        for (int n = 0; n < 16; n++) {
            int r = rl + n*16;
            float4 p = *(const float4*)(Pb + (size_t)sj[r]*64 + q*4);
            float dx = sdx[r], dy = sdy[r], dz = sdz[r];
            float y0 = p.x + dx*wx.x + dy*wy.x + dz*wz.x;
            float yb = p.y + dx*wx.y + dy*wy.y + dz*wz.y;
            float yc = p.z + dx*wx.z + dy*wy.z + dz*wz.z;
            float yd = p.w + dx*wx.w + dy*wy.w + dz*wz.w;
            As[(q*4+0)*P1 + r] = fmaxf(y0*sc[0] + sh[0], 0.0f);
            As[(q*4+1)*P1 + r] = fmaxf(yb*sc[1] + sh[1], 0.0f);
            As[(q*4+2)*P1 + r] = fmaxf(yc*sc[2] + sh[2], 0.0f);
            As[(q*4+3)*P1 + r] = fmaxf(yd*sc[3] + sh[3], 0.0f);
        }
    }
    __syncthreads();
    int rg = tid >> 3, cg = tid & 7;
    ull acc2[8][4];
    #pragma unroll
    for (int i = 0; i < 8; i++)
        #pragma unroll
        for (int p = 0; p < 4; p++) acc2[i][p] = 0ull;
    {
        const float* ap = As + rg*8;
        const char* wlb = (const char*)(Wlo + cg*4);
        const char* whb = (const char*)(Whi + cg*4);
        #pragma unroll 4
        for (int k = 0; k < 64; ++k) {
            float4 a0 = *(const float4*)(ap + k*P1);
            float4 a1 = *(const float4*)(ap + k*P1 + 4);
            ulonglong2 w0v = *(const ulonglong2*)(wlb + k*128);
            ulonglong2 w1v = *(const ulonglong2*)(whb + k*128);
            ull pa;
            pa = pack2(a0.x);
            ffma2(acc2[0][0], pa, w0v.x); ffma2(acc2[0][1], pa, w0v.y);
            ffma2(acc2[0][2], pa, w1v.x); ffma2(acc2[0][3], pa, w1v.y);
            pa = pack2(a0.y);
            ffma2(acc2[1][0], pa, w0v.x); ffma2(acc2[1][1], pa, w0v.y);
            ffma2(acc2[1][2], pa, w1v.x); ffma2(acc2[1][3], pa, w1v.y);
            pa = pack2(a0.z);
            ffma2(acc2[2][0], pa, w0v.x); ffma2(acc2[2][1], pa, w0v.y);
            ffma2(acc2[2][2], pa, w1v.x); ffma2(acc2[2][3], pa, w1v.y);
            pa = pack2(a0.w);
            ffma2(acc2[3][0], pa, w0v.x); ffma2(acc2[3][1], pa, w0v.y);
            ffma2(acc2[3][2], pa, w1v.x); ffma2(acc2[3][3], pa, w1v.y);
            pa = pack2(a1.x);
            ffma2(acc2[4][0], pa, w0v.x); ffma2(acc2[4][1], pa, w0v.y);
            ffma2(acc2[4][2], pa, w1v.x); ffma2(acc2[4][3], pa, w1v.y);
            pa = pack2(a1.y);
            ffma2(acc2[5][0], pa, w0v.x); ffma2(acc2[5][1], pa, w0v.y);
            ffma2(acc2[5][2], pa, w1v.x); ffma2(acc2[5][3], pa, w1v.y);
            pa = pack2(a1.z);
            ffma2(acc2[6][0], pa, w0v.x); ffma2(acc2[6][1], pa, w0v.y);
            ffma2(acc2[6][2], pa, w1v.x); ffma2(acc2[6][3], pa, w1v.y);
            pa = pack2(a1.w);
            ffma2(acc2[7][0], pa, w0v.x); ffma2(acc2[7][1], pa, w0v.y);
            ffma2(acc2[7][2], pa, w1v.x); ffma2(acc2[7][3], pa, w1v.y);
        }
    }
    float acc[8][8];
    #pragma unroll
    for (int i = 0; i < 8; i++)
        #pragma unroll
        for (int p = 0; p < 4; p++) {
            float2 u = unpack2(acc2[i][p]);
            acc[i][2*p] = u.x; acc[i][2*p+1] = u.y;
        }
    float bb[8];
    #pragma unroll
    for (int j = 0; j < 8; j++) bb[j] = b1[cg*8 + j];
    #pragma unroll
    for (int i = 0; i < 8; i++)
        #pragma unroll
        for (int j = 0; j < 8; j++) acc[i][j] += bb[j];
    #pragma unroll
    for (int i = 0; i < 8; i++) {
        size_t row = (size_t)(m0 + rg*8 + i);
        float4 v0 = make_float4(acc[i][0], acc[i][1], acc[i][2], acc[i][3]);
        float4 v1 = make_float4(acc[i][4], acc[i][5], acc[i][6], acc[i][7]);
        *(float4*)&g_y1[row*64 + cg*8]     = v0;
        *(float4*)&g_y1[row*64 + cg*8 + 4] = v1;
    }
    float s8[8], q8[8];
    #pragma unroll
    for (int j = 0; j < 8; j++) { s8[j] = 0.0f; q8[j] = 0.0f; }
    #pragma unroll
    for (int i = 0; i < 8; i++)
        #pragma unroll
        for (int j = 0; j < 8; j++) { s8[j] += acc[i][j]; q8[j] += acc[i][j]*acc[i][j]; }
    __syncthreads();
    float* rS = As;
    float* rQ = As + 64*33;
    #pragma unroll
    for (int j = 0; j < 8; j++) {
        rS[(cg*8 + j)*33 + rg] = s8[j];
        rQ[(cg*8 + j)*33 + rg] = q8[j];
    }
    __syncthreads();
    if (tid < 64) {
        float s = 0.0f, q = 0.0f;
        #pragma unroll 8
        for (int r = 0; r < 32; r++) { s += rS[tid*33 + r]; q += rQ[tid*33 + r]; }
        g_pS[blockIdx.x*64 + tid] = s;
        g_pQ[blockIdx.x*64 + tid] = q;
    }
}

// ---------------------------------------------------------------------------
// 6) layer2: WMMA bf16 3-term split (Ahi*Bhi + Ahi*Blo + Alo*Bhi), fp32 acc.
//    128x128 tile per block, 8 warps (one 16-row strip each).
// ---------------------------------------------------------------------------
__global__ void __launch_bounds__(256, 1)
gemm2_kernel(const float* __restrict__ w2, const float* __restrict__ b2,
             const float* __restrict__ gam1, const float* __restrict__ bet1) {
    extern __shared__ __align__(1024) char smem[];
    // phase 1 layout:
    //   Ahi bf16[128][AP]  @ 0       (18432 B)
    //   Alo bf16[128][AP]  @ 18432   (18432 B)
    //   Bhi bf16[64][BP]   @ 36864   (17408 B)
    //   Blo bf16[64][BP]   @ 54272   (17408 B)   -> 71680
    // phase 2 (after mma): D f32[128][DP] @ 0    (69632 B)
    // coeffs @ 71680: sc[64], sh[64], b2[128]    (1024 B)
    // partials @ 72704: pS2[2][128], pQ2[2][128] (2048 B)   total 74752
    __nv_bfloat16* Ahi = (__nv_bfloat16*)smem;
    __nv_bfloat16* Alo = Ahi + 128*AP;
    __nv_bfloat16* Bhi = (__nv_bfloat16*)(smem + 36864);
    __nv_bfloat16* Blo = Bhi + 64*BP;
    float* s_sc = (float*)(smem + 71680);
    float* s_sh = s_sc + 64;
    float* s_b2 = s_sh + 64;
    float* pS2  = (float*)(smem + 72704);
    float* pQ2  = pS2 + 256;
    int tid = threadIdx.x;
    int m0  = blockIdx.x * 128;
    if (tid < 64) {
        float scv = g_rs[tid]*gam1[tid];
        s_sc[tid] = scv;
        s_sh[tid] = bet1[tid] - g_mu[tid]*scv;
    }
    if (tid < 128) s_b2[tid] = b2[tid];
    // B fill: w2 [64 k][128 n] -> Bhi/Blo
    for (int i = tid; i < 64*128; i += 256) {
        int k = i >> 7, n = i & 127;
        float v = w2[i];
        __nv_bfloat16 h = __float2bfloat16(v);
        __nv_bfloat16 l = __float2bfloat16(v - __bfloat162float(h));
        Bhi[k*BP + n] = h;
        Blo[k*BP + n] = l;
    }
    __syncthreads();                 // s_sc/s_sh ready for A fill
    // A fill: BN1+ReLU(y1) -> bf16 hi/lo
    for (int i = tid; i < 128*16; i += 256) {
        int r = i >> 4, qq = i & 15;
        float4 p = *(const float4*)(g_y1 + (size_t)(m0 + r)*64 + qq*4);
        int c = qq*4;
        float v0 = fmaxf(p.x*s_sc[c]   + s_sh[c],   0.0f);
        float v1 = fmaxf(p.y*s_sc[c+1] + s_sh[c+1], 0.0f);
        float v2 = fmaxf(p.z*s_sc[c+2] + s_sh[c+2], 0.0f);
        float v3 = fmaxf(p.w*s_sc[c+3] + s_sh[c+3], 0.0f);
        __nv_bfloat16 h0 = __float2bfloat16(v0);
        __nv_bfloat16 h1 = __float2bfloat16(v1);
        __nv_bfloat16 h2 = __float2bfloat16(v2);
        __nv_bfloat16 h3 = __float2bfloat16(v3);
        __nv_bfloat162* ah = (__nv_bfloat162*)(Ahi + r*AP + c);
        ah[0] = __nv_bfloat162(h0, h1);
        ah[1] = __nv_bfloat162(h2, h3);
        __nv_bfloat16 l0 = __float2bfloat16(v0 - __bfloat162float(h0));
        __nv_bfloat16 l1 = __float2bfloat16(v1 - __bfloat162float(h1));
        __nv_bfloat16 l2 = __float2bfloat16(v2 - __bfloat162float(h2));
        __nv_bfloat16 l3 = __float2bfloat16(v3 - __bfloat162float(h3));
        __nv_bfloat162* al = (__nv_bfloat162*)(Alo + r*AP + c);
        al[0] = __nv_bfloat162(l0, l1);
        al[1] = __nv_bfloat162(l2, l3);
    }
    __syncthreads();
    int w = tid >> 5;                // warp -> 16-row strip
    wmma::fragment<wmma::accumulator, 16, 16, 16, float> acc[8];
    #pragma unroll
    for (int t = 0; t < 8; t++) wmma::fill_fragment(acc[t], 0.0f);
    #pragma unroll
    for (int ks = 0; ks < 4; ks++) {
        wmma::fragment<wmma::matrix_a, 16, 16, 16, __nv_bfloat16, wmma::row_major> ah, al;
        wmma::load_matrix_sync(ah, Ahi + (w*16)*AP + ks*16, AP);
        wmma::load_matrix_sync(al, Alo + (w*16)*AP + ks*16, AP);
        #pragma unroll
        for (int t = 0; t < 8; t++) {
            wmma::fragment<wmma::matrix_b, 16, 16, 16, __nv_bfloat16, wmma::row_major> bh, bl;
            wmma::load_matrix_sync(bh, Bhi + (ks*16)*BP + t*16, BP);
            wmma::mma_sync(acc[t], ah, bh, acc[t]);
            wmma::mma_sync(acc[t], al, bh, acc[t]);
            wmma::load_matrix_sync(bl, Blo + (ks*16)*BP + t*16, BP);
            wmma::mma_sync(acc[t], ah, bl, acc[t]);
        }
    }
    __syncthreads();                 // done reading A/B smem
    float* D = (float*)smem;         // [128][DP]
    #pragma unroll
    for (int t = 0; t < 8; t++)
        wmma::store_matrix_sync(D + (w*16)*DP + t*16, acc[t], DP, wmma::mem_row_major);
    __syncthreads();
    // stats + group extrema from D (+bias)
    {
        int c  = tid & 127;
        int hf = tid >> 7;           // rows hf*64 .. hf*64+63 (2 groups)
        float bias = s_b2[c];
        float s = 0.0f, q = 0.0f;
        #pragma unroll
        for (int g = 0; g < 2; g++) {
            int r0 = hf*64 + g*32;
            float mx = -1e30f, mn = 1e30f;
            #pragma unroll 4
            for (int r = r0; r < r0 + 32; r++) {
                float v = D[r*DP + c] + bias;
                s += v; q += v*v;
                mx = fmaxf(mx, v);
                mn = fminf(mn, v);
            }
            size_t grp = (size_t)blockIdx.x*4 + hf*2 + g;
            g_gmax[grp*128 + c] = mx;
            g_gmin[grp*128 + c] = mn;
        }
        pS2[hf*128 + c] = s;
        pQ2[hf*128 + c] = q;
    }
    __syncthreads();
    if (tid < 128) {
        g_pS[blockIdx.x*128 + tid] = pS2[tid] + pS2[128 + tid];
        g_pQ[blockIdx.x*128 + tid] = pQ2[tid] + pQ2[128 + tid];
    }
}

// ---------------------------------------------------------------------------
// 7) finalize stats
// ---------------------------------------------------------------------------
__global__ void finalize_stats_kernel(int C, int nblk) {
    __shared__ double shs[512], shq[512];
    int tid = threadIdx.x;
    int c   = tid & (C - 1);
    int rep = tid / C;
    int nrep = 512 / C;
    int per  = nblk / nrep;
    double s = 0.0, q = 0.0;
    for (int b = rep*per; b < (rep+1)*per; b++) {
        s += (double)g_pS[b*C + c];
        q += (double)g_pQ[b*C + c];
    }
    shs[tid] = s; shq[tid] = q;
    __syncthreads();
    if (rep == 0) {
        for (int r = 1; r < nrep; r++) { s += shs[r*C + c]; q += shq[r*C + c]; }
        double n = (double)M_TOTAL;
        double m = s / n;
        double var = q / n - m*m;
        g_mu[c] = (float)m;
        g_rs[c] = (float)(1.0 / sqrt(var + 1e-5));
    }
}

// ---------------------------------------------------------------------------
// 8) final: BN2+ReLU on group extrema, transpose -> out [B,128,NP]
// ---------------------------------------------------------------------------
__global__ void final_out_kernel(const float* __restrict__ gam2,
                                 const float* __restrict__ bet2,
                                 float* __restrict__ out) {
    extern __shared__ float sh[];
    int b  = blockIdx.x;
    int s0 = blockIdx.y * 128;
    int tid = threadIdx.x;
    for (int i = tid; i < 128*128; i += 256) {
        int s = i >> 7, c = i & 127;
        float slope = g_rs[c]*gam2[c];
        size_t gidx = ((size_t)(b*NP + s0 + s))*128 + c;
        float raw = (slope >= 0.0f) ? g_gmax[gidx] : g_gmin[gidx];
        float v = (raw - g_mu[c])*slope + bet2[c];
        sh[c*129 + s] = fmaxf(v, 0.0f);
    }
    __syncthreads();
    float* ob = out + (size_t)BB*3*NP + (size_t)b*128*NP + s0;
    for (int i = tid; i < 128*128; i += 256) {
        int c = i >> 7, s = i & 31 | ((i & 96) );
        // NOTE: simple transpose below (identical to prior rounds)
        c = i >> 7; s = i & 127;
        ob[(size_t)c*NP + s] = sh[c*129 + s];
    }
}

// ---------------------------------------------------------------------------
extern "C" void kernel_launch(void* const* d_in, const int* in_sizes, int n_in,
                              void* d_out, int out_size) {
    const float* xyz = (const float*)d_in[0];
    const float* pts = (const float*)d_in[1];
    const float* w0  = (const float*)d_in[2];
    const float* b0  = (const float*)d_in[3];
    const float* g0  = (const float*)d_in[4];
    const float* be0 = (const float*)d_in[5];
    const float* w1  = (const float*)d_in[6];
    const float* b1  = (const float*)d_in[7];
    const float* g1  = (const float*)d_in[8];
    const float* be1 = (const float*)d_in[9];
    const float* w2  = (const float*)d_in[10];
    const float* b2  = (const float*)d_in[11];
    const float* g2  = (const float*)d_in[12];
    const float* be2 = (const float*)d_in[13];
    float* out = (float*)d_out;

    const int smemP = (64*PP + 64*64) * 4;       // 50176 B
    const int smem1 = (64*P1 + 64*64) * 4;       // 82944 B
    const int smem2 = 74752;
    const int smemF = 128*129*4;                 // 66048 B
    cudaFuncSetAttribute(pgemm_kernel, cudaFuncAttributeMaxDynamicSharedMemorySize, smemP);
    cudaFuncSetAttribute(gemm1_kernel, cudaFuncAttributeMaxDynamicSharedMemorySize, smem1);
    cudaFuncSetAttribute(gemm2_kernel, cudaFuncAttributeMaxDynamicSharedMemorySize, smem2);
    cudaFuncSetAttribute(final_out_kernel, cudaFuncAttributeMaxDynamicSharedMemorySize, smemF);

    fps_kernel<<<16, 1024>>>(xyz, out);
    ball_query_kernel<<<2048, 256>>>(xyz);
    pgemm_kernel<<<512, 256, smemP>>>(pts, w0, b0);

    stats0_kernel<<<2048, 256>>>(xyz, w0);
    finalize_stats_kernel<<<1, 512>>>(64, 2048);

    gemm1_kernel<<<2048, 256, smem1>>>(xyz, w0, w1, b1, g0, be0);
    finalize_stats_kernel<<<1, 512>>>(64, 2048);

    gemm2_kernel<<<4096, 256, smem2>>>(w2, b2, g1, be1);
    finalize_stats_kernel<<<1, 512>>>(128, 4096);

    final_out_kernel<<<dim3(16, 8), 256, smemF>>>(g2, be2, out);
}

// round 13
// speedup vs baseline: 1.0948x; 1.0149x over previous
#include <cuda_runtime.h>
#include <math.h>
#include <stdint.h>

#define BB 16
#define NN 4096
#define NP 1024
#define NS 32
#define M_TOTAL (BB*NP*NS)   /* 524288 */
#define PP  132              /* pgemm A pitch */
#define P1  260              /* gemm1 A pitch (256 rows + pad) */
#define P2D 264              /* gemm2 A pitch (128 rows DUPLICATED + pad) */

typedef unsigned long long ull;

// ---------------------------------------------------------------------------
// Packed f32x2 helpers (bit-identical to 2x scalar fma.rn)
// ---------------------------------------------------------------------------
__device__ __forceinline__ void ffma2(ull& acc, ull a, ull w) {
    asm("fma.rn.f32x2 %0, %1, %2, %0;" : "+l"(acc) : "l"(a), "l"(w));
}
__device__ __forceinline__ ull pack2(float x) {
    ull r;
    asm("mov.b64 %0, {%1, %1};" : "=l"(r) : "f"(x));
    return r;
}
__device__ __forceinline__ float2 unpack2(ull v) {
    float2 r;
    asm("mov.b64 {%0, %1}, %2;" : "=f"(r.x), "=f"(r.y) : "l"(v));
    return r;
}

// ---------------------------------------------------------------------------
// Scratch
// ---------------------------------------------------------------------------
__device__ float g_P[(size_t)BB*NN*64];
__device__ float g_new_xyz[BB*NP*3];
__device__ int   g_idx[M_TOTAL];
__device__ float g_y1[(size_t)M_TOTAL*64];
__device__ float g_gmax[(size_t)BB*NP*128];
__device__ float g_gmin[(size_t)BB*NP*128];
__device__ float g_pS[4096*128];
__device__ float g_pQ[4096*128];
__device__ float g_mu[128];
__device__ float g_rs[128];
__device__ int   g_ctr;

// ---------------------------------------------------------------------------
// 1) FPS: 1024 thr, 4 pts/thread, one barrier per iteration
// ---------------------------------------------------------------------------
__global__ void __launch_bounds__(1024, 1)
fps_kernel(const float* __restrict__ xyz, float* __restrict__ out) {
    int b = blockIdx.x, tid = threadIdx.x;
    int lane = tid & 31, wp = tid >> 5;
    const float* xb = xyz + (size_t)b*3*NN;
    float px[4], py[4], pz[4], dd[4];
    #pragma unroll
    for (int i = 0; i < 4; i++) {
        int n = tid + i*1024;
        px[i] = xb[n]; py[i] = xb[NN+n]; pz[i] = xb[2*NN+n];
        dd[i] = 1e10f;
    }
    __shared__ unsigned s_wv[2][32];
    __shared__ int      s_wi[2][32];
    __shared__ int      s_fps[NP];
    if (tid == 0) s_fps[0] = 0;
    int far = 0;
    for (int it = 1; it < NP; ++it) {
        float cx = __ldg(xb + far);
        float cy = __ldg(xb + NN + far);
        float cz = __ldg(xb + 2*NN + far);
        unsigned bv = 0u, bi = 0x7fffffffu;
        #pragma unroll
        for (int i = 0; i < 4; i++) {
            float dx = __fsub_rn(px[i], cx);
            float dy = __fsub_rn(py[i], cy);
            float dz = __fsub_rn(pz[i], cz);
            float d  = __fadd_rn(__fadd_rn(__fmul_rn(dx,dx), __fmul_rn(dy,dy)),
                                 __fmul_rn(dz,dz));
            dd[i] = fminf(dd[i], d);
            unsigned vb = __float_as_uint(dd[i]);
            if (vb > bv) { bv = vb; bi = (unsigned)(tid + i*1024); }
        }
        unsigned wmax = __reduce_max_sync(0xffffffffu, bv);
        unsigned cand = (bv == wmax) ? bi : 0x7fffffffu;
        unsigned wi   = __reduce_min_sync(0xffffffffu, cand);
        int buf = it & 1;
        if (lane == 0) { s_wv[buf][wp] = wmax; s_wi[buf][wp] = (int)wi; }
        __syncthreads();
        unsigned v  = s_wv[buf][lane];
        unsigned ix = (unsigned)s_wi[buf][lane];
        unsigned m2 = __reduce_max_sync(0xffffffffu, v);
        unsigned c2 = (v == m2) ? ix : 0x7fffffffu;
        far = (int)__reduce_min_sync(0xffffffffu, c2);
        if (tid == 0) s_fps[it] = far;
    }
    __syncthreads();
    for (int s = tid; s < NP; s += 1024) {
        int j = s_fps[s];
        float x = xb[j], y = xb[NN+j], z = xb[2*NN+j];
        out[(size_t)b*3*NP + s]        = x;
        out[(size_t)b*3*NP + NP + s]   = y;
        out[(size_t)b*3*NP + 2*NP + s] = z;
        float* nx = g_new_xyz + ((size_t)b*NP + s)*3;
        nx[0] = x; nx[1] = y; nx[2] = z;
    }
}

// ---------------------------------------------------------------------------
// 2) Fused ball query + y0 stats + last-block finalize.
//    8 warps/block: warp w handles centroid blockIdx*8+w. Indices parked in
//    smem, then stats of y0 = P[j] + dxyz.W0[0:3] computed in-block.
// ---------------------------------------------------------------------------
__global__ void __launch_bounds__(256)
ballstats_kernel(const float* __restrict__ xyz, const float* __restrict__ w0) {
    __shared__ int   sj[256];
    __shared__ float sdx[256], sdy[256], sdz[256];
    __shared__ __align__(16) float s_w0[192];
    __shared__ float redS[64*17], redQ[64*17];
    __shared__ double shs[256], shq[256];
    __shared__ int s_last;
    int tid = threadIdx.x;
    int w   = tid >> 5, lane = tid & 31;
    int cidx = blockIdx.x*8 + w;          // = b*NP + s  (8 | NP so b uniform)
    int b    = cidx >> 10;
    const float* xb = xyz + (size_t)b*3*NN;
    if (tid < 192) s_w0[tid] = w0[tid];
    // ---- ball query (one warp per centroid) ----
    {
        const float* nx = g_new_xyz + (size_t)cidx*3;
        float cx = nx[0], cy = nx[1], cz = nx[2];
        float ssrc = __fadd_rn(__fadd_rn(__fmul_rn(cx,cx), __fmul_rn(cy,cy)),
                               __fmul_rn(cz,cz));
        const float R2 = 0.04f;
        int cnt = 0, first = -1;
        int* op = g_idx + (size_t)cidx*NS;
        for (int j0 = 0; j0 < NN && cnt < NS; j0 += 32) {
            int j = j0 + lane;
            float x = xb[j], y = xb[NN+j], z = xb[2*NN+j];
            float sdst = __fadd_rn(__fadd_rn(__fmul_rn(x,x), __fmul_rn(y,y)), __fmul_rn(z,z));
            float dot  = __fadd_rn(__fadd_rn(__fmul_rn(cx,x), __fmul_rn(cy,y)), __fmul_rn(cz,z));
            float d = __fadd_rn(__fadd_rn(__fmul_rn(-2.0f, dot), ssrc), sdst);
            bool in = !(d > R2);
            unsigned m = __ballot_sync(0xffffffffu, in);
            if (first < 0 && m) first = j0 + __ffs(m) - 1;
            if (in) {
                int slot = cnt + __popc(m & ((1u << lane) - 1u));
                if (slot < NS) { op[slot] = j; sj[w*32 + slot] = j; }
            }
            cnt += __popc(m);
        }
        if (cnt < NS) {
            if (first < 0) first = NN - 1;
            for (int slot = cnt + lane; slot < NS; slot += 32) {
                op[slot] = first; sj[w*32 + slot] = first;
            }
        }
    }
    __syncthreads();
    // ---- dxyz per row ----
    {
        int r = tid;
        int j = sj[r];
        const float* nx = g_new_xyz + (size_t)(blockIdx.x*8 + (r >> 5))*3;
        sdx[r] = __fsub_rn(xb[j],      nx[0]);
        sdy[r] = __fsub_rn(xb[NN+j],   nx[1]);
        sdz[r] = __fsub_rn(xb[2*NN+j], nx[2]);
    }
    __syncthreads();
    // ---- stats of y0 ----
    {
        int q  = tid >> 4;
        int rl = tid & 15;
        float4 wx = *(const float4*)(s_w0 + q*4);
        float4 wy = *(const float4*)(s_w0 + 64 + q*4);
        float4 wz = *(const float4*)(s_w0 + 128 + q*4);
        float sx=0,sy=0,sz=0,sw=0, qx=0,qy=0,qz=0,qw=0;
        const float* Pb = g_P + (size_t)b*NN*64;
        for (int n = 0; n < 16; n++) {
            int r = rl + n*16;
            float4 p = *(const float4*)(Pb + (size_t)sj[r]*64 + q*4);
            float dx = sdx[r], dy = sdy[r], dz = sdz[r];
            float yx = p.x + dx*wx.x + dy*wy.x + dz*wz.x;
            float yy = p.y + dx*wx.y + dy*wy.y + dz*wz.y;
            float yz = p.z + dx*wx.z + dy*wy.z + dz*wz.z;
            float yw = p.w + dx*wx.w + dy*wy.w + dz*wz.w;
            sx += yx; sy += yy; sz += yz; sw += yw;
            qx += yx*yx; qy += yy*yy; qz += yz*yz; qw += yw*yw;
        }
        redS[(4*q+0)*17 + rl] = sx; redQ[(4*q+0)*17 + rl] = qx;
        redS[(4*q+1)*17 + rl] = sy; redQ[(4*q+1)*17 + rl] = qy;
        redS[(4*q+2)*17 + rl] = sz; redQ[(4*q+2)*17 + rl] = qz;
        redS[(4*q+3)*17 + rl] = sw; redQ[(4*q+3)*17 + rl] = qw;
    }
    __syncthreads();
    if (tid < 64) {
        float ss = 0.0f, sq = 0.0f;
        #pragma unroll
        for (int u = 0; u < 16; u++) { ss += redS[tid*17+u]; sq += redQ[tid*17+u]; }
        g_pS[blockIdx.x*64 + tid] = ss;
        g_pQ[blockIdx.x*64 + tid] = sq;
    }
    __syncthreads();
    if (tid == 0) {
        __threadfence();
        int o = atomicAdd(&g_ctr, 1);
        s_last = (o == 2047);
    }
    __syncthreads();
    if (s_last) {
        // finalize y0 stats (256 threads: 4 reps x 64 channels)
        int c = tid & 63, rep = tid >> 6;
        double s = 0.0, q = 0.0;
        for (int b2 = rep*512; b2 < (rep+1)*512; b2++) {
            s += (double)g_pS[b2*64 + c];
            q += (double)g_pQ[b2*64 + c];
        }
        shs[tid] = s; shq[tid] = q;
        __syncthreads();
        if (rep == 0) {
            #pragma unroll
            for (int r2 = 1; r2 < 4; r2++) { s += shs[r2*64 + c]; q += shq[r2*64 + c]; }
            double n = (double)M_TOTAL;
            double m = s / n;
            double var = q / n - m*m;
            g_mu[c] = (float)m;
            g_rs[c] = (float)(1.0 / sqrt(var + 1e-5));
        }
        if (tid == 0) g_ctr = 0;      // reset for next graph replay
    }
}

// ---------------------------------------------------------------------------
#define FMA8(a, w0, w1, accrow) \
    accrow[0] += a*w0.x; accrow[1] += a*w0.y; accrow[2] += a*w0.z; accrow[3] += a*w0.w; \
    accrow[4] += a*w1.x; accrow[5] += a*w1.y; accrow[6] += a*w1.z; accrow[7] += a*w1.w;

__device__ __forceinline__ void fill_w64(float* Wlo, float* Whi,
                                         const float* __restrict__ w, int ldw,
                                         int c0, int tid) {
    for (int i = tid; i < 64*64; i += 256) {
        int k = i >> 6, c = i & 63;
        float v = w[k*ldw + c0 + c];
        int cgg = c >> 3, t = c & 7;
        if (t < 4) Wlo[k*32 + cgg*4 + t]     = v;
        else       Whi[k*32 + cgg*4 + t - 4] = v;
    }
}

// ---------------------------------------------------------------------------
// 3) P = pts^T @ W0[3:67] + b0
// ---------------------------------------------------------------------------
__global__ void __launch_bounds__(256, 4)
pgemm_kernel(const float* __restrict__ pts, const float* __restrict__ w0,
             const float* __restrict__ b0) {
    extern __shared__ __align__(16) float sm[];
    float* As  = sm;
    float* Wlo = sm + 64*PP;
    float* Whi = Wlo + 64*32;
    int tid = threadIdx.x;
    int bx  = blockIdx.x;
    int b   = bx >> 5;
    int n0  = (bx & 31) * 128;
    fill_w64(Wlo, Whi, w0 + 3*64, 64, 0, tid);
    const float* pb = pts + (size_t)b*64*NN;
    for (int i = tid; i < 64*128; i += 256) {
        int c = i >> 7, r = i & 127;
        As[c*PP + r] = pb[(size_t)c*NN + n0 + r];
    }
    __syncthreads();
    int rg = tid >> 3, cg = tid & 7;
    float acc[4][8];
    #pragma unroll
    for (int i = 0; i < 4; i++)
        #pragma unroll
        for (int j = 0; j < 8; j++) acc[i][j] = 0.0f;
    {
        const float* ap = As + rg*4;
        const float* wl = Wlo + cg*4;
        const float* wh = Whi + cg*4;
        #pragma unroll 8
        for (int k = 0; k < 64; ++k) {
            float4 a  = *(const float4*)(ap + k*PP);
            float4 w0v = *(const float4*)(wl + k*32);
            float4 w1v = *(const float4*)(wh + k*32);
            FMA8(a.x, w0v, w1v, acc[0]);
            FMA8(a.y, w0v, w1v, acc[1]);
            FMA8(a.z, w0v, w1v, acc[2]);
            FMA8(a.w, w0v, w1v, acc[3]);
        }
    }
    float bb[8];
    #pragma unroll
    for (int j = 0; j < 8; j++) bb[j] = b0[cg*8 + j];
    #pragma unroll
    for (int i = 0; i < 4; i++) {
        size_t row = (size_t)b*NN + n0 + rg*4 + i;
        float4 v0 = make_float4(acc[i][0]+bb[0], acc[i][1]+bb[1], acc[i][2]+bb[2], acc[i][3]+bb[3]);
        float4 v1 = make_float4(acc[i][4]+bb[4], acc[i][5]+bb[5], acc[i][6]+bb[6], acc[i][7]+bb[7]);
        *(float4*)&g_P[row*64 + cg*8]     = v0;
        *(float4*)&g_P[row*64 + cg*8 + 4] = v1;
    }
}

// ---------------------------------------------------------------------------
// 5) layer1: 256x64 tile, f32x2 8x8 acc. A = BN0+ReLU(y0 on the fly).
// ---------------------------------------------------------------------------
__global__ void __launch_bounds__(256, 2)
gemm1_kernel(const float* __restrict__ xyz, const float* __restrict__ w0,
             const float* __restrict__ w1, const float* __restrict__ b1,
             const float* __restrict__ gam0, const float* __restrict__ bet0) {
    extern __shared__ __align__(16) float sm[];
    float* As  = sm;                 // [64][P1]
    float* Wlo = sm + 64*P1;         // [64][32]
    float* Whi = Wlo + 64*32;
    __shared__ float sdx[256], sdy[256], sdz[256];
    __shared__ int   sj[256];
    __shared__ __align__(16) float s_w0[192];
    int tid = threadIdx.x;
    int m0  = blockIdx.x * 256;
    int b   = m0 >> 15;
    fill_w64(Wlo, Whi, w1, 64, 0, tid);
    if (tid < 192) s_w0[tid] = w0[tid];
    {
        int r = tid;
        int j = g_idx[m0 + r];
        sj[r] = j;
        const float* xb = xyz + (size_t)b*3*NN;
        const float* nx = g_new_xyz + (size_t)((m0 + r) >> 5)*3;
        sdx[r] = __fsub_rn(xb[j],      nx[0]);
        sdy[r] = __fsub_rn(xb[NN+j],   nx[1]);
        sdz[r] = __fsub_rn(xb[2*NN+j], nx[2]);
    }
    __syncthreads();
    {
        int q  = tid >> 4;
        int rl = tid & 15;
        float4 wx = *(const float4*)(s_w0 + q*4);
        float4 wy = *(const float4*)(s_w0 + 64 + q*4);
        float4 wz = *(const float4*)(s_w0 + 128 + q*4);
        float sc[4], sh[4];
        #pragma unroll
        for (int t = 0; t < 4; t++) {
            int k = q*4 + t;
            sc[t] = g_rs[k]*gam0[k];
            sh[t] = bet0[k] - g_mu[k]*sc[t];
        }
        const float* Pb = g_P + (size_t)b*NN*64;
        for (int n = 0; n < 16; n++) {
            int r = rl + n*16;
            float4 p = *(const float4*)(Pb + (size_t)sj[r]*64 + q*4);
            float dx = sdx[r], dy = sdy[r], dz = sdz[r];
            float y0 = p.x + dx*wx.x + dy*wy.x + dz*wz.x;
            float yb = p.y + dx*wx.y + dy*wy.y + dz*wz.y;
            float yc = p.z + dx*wx.z + dy*wy.z + dz*wz.z;
            float yd = p.w + dx*wx.w + dy*wy.w + dz*wz.w;
            As[(q*4+0)*P1 + r] = fmaxf(y0*sc[0] + sh[0], 0.0f);
            As[(q*4+1)*P1 + r] = fmaxf(yb*sc[1] + sh[1], 0.0f);
            As[(q*4+2)*P1 + r] = fmaxf(yc*sc[2] + sh[2], 0.0f);
            As[(q*4+3)*P1 + r] = fmaxf(yd*sc[3] + sh[3], 0.0f);
        }
    }
    __syncthreads();
    int rg = tid >> 3, cg = tid & 7;
    ull acc2[8][4];
    #pragma unroll
    for (int i = 0; i < 8; i++)
        #pragma unroll
        for (int p = 0; p < 4; p++) acc2[i][p] = 0ull;
    {
        const float* ap = As + rg*8;
        const char* wlb = (const char*)(Wlo + cg*4);
        const char* whb = (const char*)(Whi + cg*4);
        #pragma unroll 4
        for (int k = 0; k < 64; ++k) {
            float4 a0 = *(const float4*)(ap + k*P1);
            float4 a1 = *(const float4*)(ap + k*P1 + 4);
            ulonglong2 w0v = *(const ulonglong2*)(wlb + k*128);
            ulonglong2 w1v = *(const ulonglong2*)(whb + k*128);
            ull pa;
            pa = pack2(a0.x);
            ffma2(acc2[0][0], pa, w0v.x); ffma2(acc2[0][1], pa, w0v.y);
            ffma2(acc2[0][2], pa, w1v.x); ffma2(acc2[0][3], pa, w1v.y);
            pa = pack2(a0.y);
            ffma2(acc2[1][0], pa, w0v.x); ffma2(acc2[1][1], pa, w0v.y);
            ffma2(acc2[1][2], pa, w1v.x); ffma2(acc2[1][3], pa, w1v.y);
            pa = pack2(a0.z);
            ffma2(acc2[2][0], pa, w0v.x); ffma2(acc2[2][1], pa, w0v.y);
            ffma2(acc2[2][2], pa, w1v.x); ffma2(acc2[2][3], pa, w1v.y);
            pa = pack2(a0.w);
            ffma2(acc2[3][0], pa, w0v.x); ffma2(acc2[3][1], pa, w0v.y);
            ffma2(acc2[3][2], pa, w1v.x); ffma2(acc2[3][3], pa, w1v.y);
            pa = pack2(a1.x);
            ffma2(acc2[4][0], pa, w0v.x); ffma2(acc2[4][1], pa, w0v.y);
            ffma2(acc2[4][2], pa, w1v.x); ffma2(acc2[4][3], pa, w1v.y);
            pa = pack2(a1.y);
            ffma2(acc2[5][0], pa, w0v.x); ffma2(acc2[5][1], pa, w0v.y);
            ffma2(acc2[5][2], pa, w1v.x); ffma2(acc2[5][3], pa, w1v.y);
            pa = pack2(a1.z);
            ffma2(acc2[6][0], pa, w0v.x); ffma2(acc2[6][1], pa, w0v.y);
            ffma2(acc2[6][2], pa, w1v.x); ffma2(acc2[6][3], pa, w1v.y);
            pa = pack2(a1.w);
            ffma2(acc2[7][0], pa, w0v.x); ffma2(acc2[7][1], pa, w0v.y);
            ffma2(acc2[7][2], pa, w1v.x); ffma2(acc2[7][3], pa, w1v.y);
        }
    }
    float acc[8][8];
    #pragma unroll
    for (int i = 0; i < 8; i++)
        #pragma unroll
        for (int p = 0; p < 4; p++) {
            float2 u = unpack2(acc2[i][p]);
            acc[i][2*p] = u.x; acc[i][2*p+1] = u.y;
        }
    float bb[8];
    #pragma unroll
    for (int j = 0; j < 8; j++) bb[j] = b1[cg*8 + j];
    #pragma unroll
    for (int i = 0; i < 8; i++)
        #pragma unroll
        for (int j = 0; j < 8; j++) acc[i][j] += bb[j];
    #pragma unroll
    for (int i = 0; i < 8; i++) {
        size_t row = (size_t)(m0 + rg*8 + i);
        float4 v0 = make_float4(acc[i][0], acc[i][1], acc[i][2], acc[i][3]);
        float4 v1 = make_float4(acc[i][4], acc[i][5], acc[i][6], acc[i][7]);
        *(float4*)&g_y1[row*64 + cg*8]     = v0;
        *(float4*)&g_y1[row*64 + cg*8 + 4] = v1;
    }
    float s8[8], q8[8];
    #pragma unroll
    for (int j = 0; j < 8; j++) { s8[j] = 0.0f; q8[j] = 0.0f; }
    #pragma unroll
    for (int i = 0; i < 8; i++)
        #pragma unroll
        for (int j = 0; j < 8; j++) { s8[j] += acc[i][j]; q8[j] += acc[i][j]*acc[i][j]; }
    __syncthreads();
    float* rS = As;
    float* rQ = As + 64*33;
    #pragma unroll
    for (int j = 0; j < 8; j++) {
        rS[(cg*8 + j)*33 + rg] = s8[j];
        rQ[(cg*8 + j)*33 + rg] = q8[j];
    }
    __syncthreads();
    if (tid < 64) {
        float s = 0.0f, q = 0.0f;
        #pragma unroll 8
        for (int r = 0; r < 32; r++) { s += rS[tid*33 + r]; q += rQ[tid*33 + r]; }
        g_pS[blockIdx.x*64 + tid] = s;
        g_pQ[blockIdx.x*64 + tid] = q;
    }
}

// ---------------------------------------------------------------------------
// 6) layer2: 128x128 tile, A stored DUPLICATED -> pure packed inner loop.
//    (R6 version — measured fastest)
// ---------------------------------------------------------------------------
__global__ void __launch_bounds__(256, 2)
gemm2_kernel(const float* __restrict__ w2, const float* __restrict__ b2,
             const float* __restrict__ gam1, const float* __restrict__ bet1) {
    extern __shared__ __align__(16) float sm[];
    float* As  = sm;                 // [64][P2D]  (values duplicated: (a,a))
    float* Wlo = sm + 64*P2D;        // [64][64]
    float* Whi = Wlo + 64*64;        // [64][64]
    int tid = threadIdx.x;
    int m0  = blockIdx.x * 128;
    for (int i = tid; i < 64*128; i += 256) {
        int k = i >> 7, c = i & 127;
        float v = w2[k*128 + c];
        int cgg = c >> 3, t = c & 7;
        if (t < 4) Wlo[k*64 + cgg*4 + t]     = v;
        else       Whi[k*64 + cgg*4 + t - 4] = v;
    }
    {
        int q  = tid >> 4;
        int rl = tid & 15;
        float sc[4], sh[4];
        #pragma unroll
        for (int t = 0; t < 4; t++) {
            int k = q*4 + t;
            sc[t] = g_rs[k]*gam1[k];
            sh[t] = bet1[k] - g_mu[k]*sc[t];
        }
        for (int n = 0; n < 8; n++) {
            int r = rl + n*16;
            float4 p = *(const float4*)(g_y1 + (size_t)(m0 + r)*64 + q*4);
            float v0 = fmaxf(p.x*sc[0] + sh[0], 0.0f);
            float v1 = fmaxf(p.y*sc[1] + sh[1], 0.0f);
            float v2 = fmaxf(p.z*sc[2] + sh[2], 0.0f);
            float v3 = fmaxf(p.w*sc[3] + sh[3], 0.0f);
            *(float2*)(As + (q*4+0)*P2D + 2*r) = make_float2(v0, v0);
            *(float2*)(As + (q*4+1)*P2D + 2*r) = make_float2(v1, v1);
            *(float2*)(As + (q*4+2)*P2D + 2*r) = make_float2(v2, v2);
            *(float2*)(As + (q*4+3)*P2D + 2*r) = make_float2(v3, v3);
        }
    }
    __syncthreads();
    int rg = tid >> 4, cg = tid & 15;
    ull acc2[8][4];
    #pragma unroll
    for (int i = 0; i < 8; i++)
        #pragma unroll
        for (int p = 0; p < 4; p++) acc2[i][p] = 0ull;
    {
        const char* ap  = (const char*)(As + rg*16);
        const char* wlb = (const char*)(Wlo + cg*4);
        const char* whb = (const char*)(Whi + cg*4);
        #pragma unroll 4
        for (int k = 0; k < 64; ++k) {
            ulonglong2 a01 = *(const ulonglong2*)(ap + k*(P2D*4));
            ulonglong2 a23 = *(const ulonglong2*)(ap + k*(P2D*4) + 16);
            ulonglong2 a45 = *(const ulonglong2*)(ap + k*(P2D*4) + 32);
            ulonglong2 a67 = *(const ulonglong2*)(ap + k*(P2D*4) + 48);
            ulonglong2 w0v = *(const ulonglong2*)(wlb + k*256);
            ulonglong2 w1v = *(const ulonglong2*)(whb + k*256);
            ffma2(acc2[0][0], a01.x, w0v.x); ffma2(acc2[0][1], a01.x, w0v.y);
            ffma2(acc2[0][2], a01.x, w1v.x); ffma2(acc2[0][3], a01.x, w1v.y);
            ffma2(acc2[1][0], a01.y, w0v.x); ffma2(acc2[1][1], a01.y, w0v.y);
            ffma2(acc2[1][2], a01.y, w1v.x); ffma2(acc2[1][3], a01.y, w1v.y);
            ffma2(acc2[2][0], a23.x, w0v.x); ffma2(acc2[2][1], a23.x, w0v.y);
            ffma2(acc2[2][2], a23.x, w1v.x); ffma2(acc2[2][3], a23.x, w1v.y);
            ffma2(acc2[3][0], a23.y, w0v.x); ffma2(acc2[3][1], a23.y, w0v.y);
            ffma2(acc2[3][2], a23.y, w1v.x); ffma2(acc2[3][3], a23.y, w1v.y);
            ffma2(acc2[4][0], a45.x, w0v.x); ffma2(acc2[4][1], a45.x, w0v.y);
            ffma2(acc2[4][2], a45.x, w1v.x); ffma2(acc2[4][3], a45.x, w1v.y);
            ffma2(acc2[5][0], a45.y, w0v.x); ffma2(acc2[5][1], a45.y, w0v.y);
            ffma2(acc2[5][2], a45.y, w1v.x); ffma2(acc2[5][3], a45.y, w1v.y);
            ffma2(acc2[6][0], a67.x, w0v.x); ffma2(acc2[6][1], a67.x, w0v.y);
            ffma2(acc2[6][2], a67.x, w1v.x); ffma2(acc2[6][3], a67.x, w1v.y);
            ffma2(acc2[7][0], a67.y, w0v.x); ffma2(acc2[7][1], a67.y, w0v.y);
            ffma2(acc2[7][2], a67.y, w1v.x); ffma2(acc2[7][3], a67.y, w1v.y);
        }
    }
    float acc[8][8];
    #pragma unroll
    for (int i = 0; i < 8; i++)
        #pragma unroll
        for (int p = 0; p < 4; p++) {
            float2 u = unpack2(acc2[i][p]);
            acc[i][2*p] = u.x; acc[i][2*p+1] = u.y;
        }
    float bb[8];
    #pragma unroll
    for (int j = 0; j < 8; j++) bb[j] = b2[cg*8 + j];
    #pragma unroll
    for (int i = 0; i < 8; i++)
        #pragma unroll
        for (int j = 0; j < 8; j++) acc[i][j] += bb[j];
    float s8[8], q8[8], mx8[8], mn8[8];
    #pragma unroll
    for (int j = 0; j < 8; j++) {
        s8[j] = acc[0][j]; q8[j] = acc[0][j]*acc[0][j];
        mx8[j] = acc[0][j]; mn8[j] = acc[0][j];
    }
    #pragma unroll
    for (int i = 1; i < 8; i++)
        #pragma unroll
        for (int j = 0; j < 8; j++) {
            s8[j] += acc[i][j]; q8[j] += acc[i][j]*acc[i][j];
            mx8[j] = fmaxf(mx8[j], acc[i][j]);
            mn8[j] = fminf(mn8[j], acc[i][j]);
        }
    __syncthreads();
    float* rS   = As;                // [128][17]
    float* rQ   = As + 128*17;
    float* rmax = Wlo;               // [16][132]
    float* rmin = Wlo + 16*132;
    #pragma unroll
    for (int j = 0; j < 8; j++) {
        rS[(cg*8 + j)*17 + rg] = s8[j];
        rQ[(cg*8 + j)*17 + rg] = q8[j];
        rmax[rg*132 + cg*8 + j] = mx8[j];
        rmin[rg*132 + cg*8 + j] = mn8[j];
    }
    __syncthreads();
    if (tid < 128) {
        float s = 0.0f, q = 0.0f;
        #pragma unroll
        for (int r = 0; r < 16; r++) { s += rS[tid*17 + r]; q += rQ[tid*17 + r]; }
        g_pS[blockIdx.x*128 + tid] = s;
        g_pQ[blockIdx.x*128 + tid] = q;
    }
    for (int i = tid; i < 512; i += 256) {
        int g = i >> 7, c = i & 127;
        float mx = rmax[(g*4 + 0)*132 + c];
        float mn = rmin[(g*4 + 0)*132 + c];
        #pragma unroll
        for (int u = 1; u < 4; u++) {
            mx = fmaxf(mx, rmax[(g*4 + u)*132 + c]);
            mn = fminf(mn, rmin[(g*4 + u)*132 + c]);
        }
        size_t grp = (size_t)blockIdx.x*4 + g;
        g_gmax[grp*128 + c] = mx;
        g_gmin[grp*128 + c] = mn;
    }
}

// ---------------------------------------------------------------------------
// 7) finalize stats (for gemm1 / gemm2 partials)
// ---------------------------------------------------------------------------
__global__ void finalize_stats_kernel(int C, int nblk) {
    __shared__ double shs[512], shq[512];
    int tid = threadIdx.x;
    int c   = tid & (C - 1);
    int rep = tid / C;
    int nrep = 512 / C;
    int per  = nblk / nrep;
    double s = 0.0, q = 0.0;
    for (int b = rep*per; b < (rep+1)*per; b++) {
        s += (double)g_pS[b*C + c];
        q += (double)g_pQ[b*C + c];
    }
    shs[tid] = s; shq[tid] = q;
    __syncthreads();
    if (rep == 0) {
        for (int r = 1; r < nrep; r++) { s += shs[r*C + c]; q += shq[r*C + c]; }
        double n = (double)M_TOTAL;
        double m = s / n;
        double var = q / n - m*m;
        g_mu[c] = (float)m;
        g_rs[c] = (float)(1.0 / sqrt(var + 1e-5));
    }
}

// ---------------------------------------------------------------------------
// 8) final: BN2+ReLU on group extrema, transpose -> out [B,128,NP]
// ---------------------------------------------------------------------------
__global__ void final_out_kernel(const float* __restrict__ gam2,
                                 const float* __restrict__ bet2,
                                 float* __restrict__ out) {
    extern __shared__ float sh[];
    int b  = blockIdx.x;
    int s0 = blockIdx.y * 128;
    int tid = threadIdx.x;
    for (int i = tid; i < 128*128; i += 256) {
        int s = i >> 7, c = i & 127;
        float slope = g_rs[c]*gam2[c];
        size_t gidx = ((size_t)(b*NP + s0 + s))*128 + c;
        float raw = (slope >= 0.0f) ? g_gmax[gidx] : g_gmin[gidx];
        float v = (raw - g_mu[c])*slope + bet2[c];
        sh[c*129 + s] = fmaxf(v, 0.0f);
    }
    __syncthreads();
    float* ob = out + (size_t)BB*3*NP + (size_t)b*128*NP + s0;
    for (int i = tid; i < 128*128; i += 256) {
        int c = i >> 7, s = i & 127;
        ob[(size_t)c*NP + s] = sh[c*129 + s];
    }
}

// ---------------------------------------------------------------------------
extern "C" void kernel_launch(void* const* d_in, const int* in_sizes, int n_in,
                              void* d_out, int out_size) {
    const float* xyz = (const float*)d_in[0];
    const float* pts = (const float*)d_in[1];
    const float* w0  = (const float*)d_in[2];
    const float* b0  = (const float*)d_in[3];
    const float* g0  = (const float*)d_in[4];
    const float* be0 = (const float*)d_in[5];
    const float* w1  = (const float*)d_in[6];
    const float* b1  = (const float*)d_in[7];
    const float* g1  = (const float*)d_in[8];
    const float* be1 = (const float*)d_in[9];
    const float* w2  = (const float*)d_in[10];
    const float* b2  = (const float*)d_in[11];
    const float* g2  = (const float*)d_in[12];
    const float* be2 = (const float*)d_in[13];
    float* out = (float*)d_out;

    const int smemP = (64*PP  + 64*64) * 4;       // 50176 B
    const int smem1 = (64*P1  + 64*64) * 4;       // 82944 B
    const int smem2 = (64*P2D + 2*64*64) * 4;     // 100352 B
    const int smemF = 128*129*4;                  // 66048 B
    cudaFuncSetAttribute(pgemm_kernel, cudaFuncAttributeMaxDynamicSharedMemorySize, smemP);
    cudaFuncSetAttribute(gemm1_kernel, cudaFuncAttributeMaxDynamicSharedMemorySize, smem1);
    cudaFuncSetAttribute(gemm2_kernel, cudaFuncAttributeMaxDynamicSharedMemorySize, smem2);
    cudaFuncSetAttribute(final_out_kernel, cudaFuncAttributeMaxDynamicSharedMemorySize, smemF);

    // order chosen so gemm1 is the 4th launch (ncu capture slot)
    pgemm_kernel<<<512, 256, smemP>>>(pts, w0, b0);          // 1
    fps_kernel<<<16, 1024>>>(xyz, out);                      // 2
    ballstats_kernel<<<2048, 256>>>(xyz, w0);                // 3 (incl. y0-stats finalize)
    gemm1_kernel<<<2048, 256, smem1>>>(xyz, w0, w1, b1, g0, be0);   // 4  <- profiled
    finalize_stats_kernel<<<1, 512>>>(64, 2048);             // 5
    gemm2_kernel<<<4096, 256, smem2>>>(w2, b2, g1, be1);     // 6
    finalize_stats_kernel<<<1, 512>>>(128, 4096);            // 7
    final_out_kernel<<<dim3(16, 8), 256, smemF>>>(g2, be2, out);    // 8
}